// round 1
// baseline (speedup 1.0000x reference)
#include <cuda_runtime.h>
#include <math.h>

#define Bb 8
#define Cc 96
#define Hh 256
#define Ww 256
#define HW 65536
#define WSZ 16
#define NWIN 256   // windows per batch (16x16)
#define DTOK 256   // tokens per window
#define SHARP 10.0f

// ---------------- scratch (device globals; no allocation) ----------------
__device__ float g_v [(size_t)Bb * Cc * HW];   // v_img
__device__ float g_fs[(size_t)Bb * Cc * HW];   // f_img + v2c accumulator
__device__ float g_mask[Bb * NWIN];            // per-window mask value

// =====================================================================
// K1/K5: conv1x1 GEMM  out[b,o,p] = bias[o] + sum_c W[o,c]*in[b,c,p]
// tile: 96 c_out x 128 consecutive pixels. 256 threads, reg tile 6x8.
// dynamic smem: W [96][97] + x [96][128]
// =====================================================================
#define GEMM_SMEM ((96 * 97 + 96 * 128) * 4)

__global__ void __launch_bounds__(256) k_gemm(const float* __restrict__ in,
                                              const float* __restrict__ Wm,
                                              const float* __restrict__ bias,
                                              float* __restrict__ out) {
    extern __shared__ float sm[];
    float* Ws = sm;              // [96][97]
    float* xs = sm + 96 * 97;    // [96][128]
    int b  = blockIdx.y;
    int p0 = blockIdx.x * 128;
    int tid = threadIdx.x;

    for (int i = tid; i < 96 * 96; i += 256) {
        int r = i / 96, c = i - r * 96;
        Ws[r * 97 + c] = Wm[i];
    }
    const float* inb = in + (size_t)b * Cc * HW + p0;
    for (int i = tid; i < 96 * 32; i += 256) {
        int c = i >> 5, q = (i & 31) << 2;
        float4 v4 = *reinterpret_cast<const float4*>(inb + (size_t)c * HW + q);
        *reinterpret_cast<float4*>(&xs[c * 128 + q]) = v4;
    }
    __syncthreads();

    int pg = tid & 15, cg = tid >> 4;
    float acc[6][8];
#pragma unroll
    for (int i = 0; i < 6; i++)
#pragma unroll
        for (int j = 0; j < 8; j++) acc[i][j] = 0.f;

#pragma unroll 8
    for (int k = 0; k < 96; k++) {
        float a[6];
#pragma unroll
        for (int i = 0; i < 6; i++) a[i] = Ws[(cg * 6 + i) * 97 + k];
        float4 x0 = *reinterpret_cast<float4*>(&xs[k * 128 + pg * 8]);
        float4 x1 = *reinterpret_cast<float4*>(&xs[k * 128 + pg * 8 + 4]);
        float xv[8] = {x0.x, x0.y, x0.z, x0.w, x1.x, x1.y, x1.z, x1.w};
#pragma unroll
        for (int i = 0; i < 6; i++)
#pragma unroll
            for (int j = 0; j < 8; j++) acc[i][j] = fmaf(a[i], xv[j], acc[i][j]);
    }

    float* outb = out + (size_t)b * Cc * HW + p0;
#pragma unroll
    for (int i = 0; i < 6; i++) {
        int o = cg * 6 + i;
        float bb = bias[o];
        float4 r0 = make_float4(acc[i][0] + bb, acc[i][1] + bb, acc[i][2] + bb, acc[i][3] + bb);
        float4 r1 = make_float4(acc[i][4] + bb, acc[i][5] + bb, acc[i][6] + bb, acc[i][7] + bb);
        *reinterpret_cast<float4*>(outb + (size_t)o * HW + pg * 8)     = r0;
        *reinterpret_cast<float4*>(outb + (size_t)o * HW + pg * 8 + 4) = r1;
    }
}

// =====================================================================
// K2: per-window t = mean_o leaky(Wt.v + bt); var(ddof=1); mask
// one block per window (2048 blocks), 256 threads = 256 pixels
// =====================================================================
__global__ void __launch_bounds__(256) k_mask(const float* __restrict__ v,
                                              const float* __restrict__ Wt,
                                              const float* __restrict__ bt,
                                              const float* __restrict__ th,
                                              float* __restrict__ mask) {
    __shared__ float Wts[24 * 96];
    __shared__ float bts[24];
    __shared__ float rs1[8], rs2[8];
    int w  = blockIdx.x;
    int b  = w >> 8, wi = w & 255;
    int wy = wi >> 4, wx = wi & 15;
    int tid = threadIdx.x;

    for (int i = tid; i < 24 * 96; i += 256) Wts[i] = Wt[i];
    if (tid < 24) bts[tid] = bt[tid];
    __syncthreads();

    int y = wy * 16 + (tid >> 4), x = wx * 16 + (tid & 15);
    const float* vp = v + (size_t)b * Cc * HW + (size_t)y * 256 + x;
    float vr[96];
#pragma unroll
    for (int c = 0; c < 96; c++) vr[c] = vp[(size_t)c * HW];

    float t = 0.f;
    for (int o = 0; o < 24; o++) {
        float s = bts[o];
        const float* wr = &Wts[o * 96];
#pragma unroll
        for (int c = 0; c < 96; c++) s = fmaf(wr[c], vr[c], s);
        t += (s >= 0.f) ? s : 0.1f * s;
    }
    t *= (1.f / 24.f);

    float s1 = t, s2 = t * t;
#pragma unroll
    for (int off = 16; off; off >>= 1) {
        s1 += __shfl_xor_sync(0xffffffffu, s1, off);
        s2 += __shfl_xor_sync(0xffffffffu, s2, off);
    }
    if ((tid & 31) == 0) { rs1[tid >> 5] = s1; rs2[tid >> 5] = s2; }
    __syncthreads();
    if (tid == 0) {
        float S1 = 0.f, S2 = 0.f;
#pragma unroll
        for (int i = 0; i < 8; i++) { S1 += rs1[i]; S2 += rs2[i]; }
        float var  = (S2 - S1 * S1 * (1.f / 256.f)) * (1.f / 255.f);
        float soft = 1.f - 1.f / (1.f + expf(-SHARP * (th[0] - var)));
        float bin  = (soft > 0.5f) ? 1.f : 0.f;
        mask[w]    = (bin - soft) + soft;   // numerically == bin (ref formula)
    }
}

// =====================================================================
// K3: window attention. Inactive window -> zero-fill fsum.
// Active: q/k projection into smem (stride-97), online softmax, f accum.
// dynamic smem: xs(->qs)[256][97] + ks[256][97]
// =====================================================================
#define ATTN_SMEM (2 * 256 * 97 * 4)

__global__ void __launch_bounds__(256) k_attn(const float* __restrict__ x,
                                              const float* __restrict__ Wq,
                                              const float* __restrict__ bq,
                                              const float* __restrict__ Wk,
                                              const float* __restrict__ bk,
                                              const float* __restrict__ mask,
                                              const float* __restrict__ v,
                                              float* __restrict__ fs) {
    extern __shared__ float sm[];
    float* xs = sm;              // [256][97], later holds q
    float* ks = sm + 256 * 97;   // [256][97]
    int w  = blockIdx.x;
    int b  = w >> 8, wi = w & 255;
    int wy = wi >> 4, wx = wi & 15;
    int y0 = wy * 16, x0 = wx * 16;
    int tid = threadIdx.x;
    float m = mask[w];
    size_t base = (size_t)b * Cc * HW;

    if (m < 0.5f) {
        // f is ~m * O(1) ~ 1e-8 here: write zeros
        for (int i = tid; i < 96 * 256; i += 256) {
            int c = i >> 8, p = i & 255;
            fs[base + (size_t)c * HW + (size_t)(y0 + (p >> 4)) * 256 + x0 + (p & 15)] = 0.f;
        }
        return;
    }

    // stage 1: load x window
    for (int i = tid; i < 96 * 256; i += 256) {
        int c = i >> 8, p = i & 255;
        xs[p * 97 + c] = x[base + (size_t)c * HW + (size_t)(y0 + (p >> 4)) * 256 + x0 + (p & 15)];
    }
    __syncthreads();

    // stage 2: q,k projection for token tid
    {
        float xr[96];
#pragma unroll
        for (int c = 0; c < 96; c++) xr[c] = xs[tid * 97 + c];
#pragma unroll 1
        for (int o = 0; o < 96; o++) {
            const float* wkp = Wk + o * 96;
            const float* wqp = Wq + o * 96;
            float sk = 0.f, sq = 0.f;
#pragma unroll
            for (int c = 0; c < 96; c++) {
                sk = fmaf(wkp[c], xr[c], sk);
                sq = fmaf(wqp[c], xr[c], sq);
            }
            ks[tid * 97 + o] = bk[o] + m * sk;
            xs[tid * 97 + o] = bq[o] + m * sq;  // safe: xr already in regs
        }
    }
    __syncthreads();

    // stage 3: online softmax stats for row tid
    float qr[96];
#pragma unroll
    for (int c = 0; c < 96; c++) qr[c] = xs[tid * 97 + c];
    float mx = -1e30f, li = 0.f;
#pragma unroll 1
    for (int j = 0; j < 256; j++) {
        const float* kj = &ks[j * 97];
        float s = 0.f;
#pragma unroll
        for (int c = 0; c < 96; c++) s = fmaf(qr[c], kj[c], s);
        float nm = fmaxf(mx, s);
        li = li * expf(mx - nm) + expf(s - nm);
        mx = nm;
    }
    float inv = 1.f / li;

    // stage 4: f accumulation in 2 channel halves (reg pressure)
    int yy = y0 + (tid >> 4), xxp = x0 + (tid & 15);
    size_t obase = base + (size_t)yy * 256 + xxp;
#pragma unroll 1
    for (int h = 0; h < 2; h++) {
        float fa[48];
#pragma unroll
        for (int c = 0; c < 48; c++) fa[c] = 0.f;
#pragma unroll 1
        for (int j = 0; j < 256; j++) {
            const float* kj = &ks[j * 97];
            float s = 0.f;
#pragma unroll
            for (int c = 0; c < 96; c++) s = fmaf(qr[c], kj[c], s);
            float p = expf(s - mx);
            size_t pj = (size_t)(y0 + (j >> 4)) * 256 + x0 + (j & 15);
            const float* vp = v + base + (size_t)(h * 48) * HW + pj;
#pragma unroll
            for (int c = 0; c < 48; c++) fa[c] = fmaf(p, vp[(size_t)c * HW], fa[c]);
        }
        float sc = inv * m;   // v1 = m * v
#pragma unroll
        for (int c = 0; c < 48; c++)
            fs[obase + (size_t)(h * 48 + c) * HW] = fa[c] * sc;
    }
}

// =====================================================================
// K4: fused depthwise conv chain: v2 = v*(1-m); y1 = dw3x3(v2,dil1);
//     y2 = dw3x3(y1,dil2); fsum += y2.  32x32 tile per (channel,batch).
// conv2 zero-pads y1 OUTSIDE the image (y1 at oob coords forced to 0).
// =====================================================================
__global__ void __launch_bounds__(256) k_dw(const float* __restrict__ v,
                                            const float* __restrict__ mask,
                                            const float* __restrict__ Wd1,
                                            const float* __restrict__ bd1,
                                            const float* __restrict__ Wd2,
                                            const float* __restrict__ bd2,
                                            float* __restrict__ fs) {
    __shared__ float vs[38][40];
    __shared__ float y1[36][40];
    int tile = blockIdx.x, c = blockIdx.y, b = blockIdx.z;
    int ty0 = (tile >> 3) * 32, tx0 = (tile & 7) * 32;
    int tid = threadIdx.x;
    const float* vc = v + ((size_t)b * Cc + c) * HW;
    const float* mb = mask + b * NWIN;

    for (int i = tid; i < 38 * 38; i += 256) {
        int r = i / 38, q = i - r * 38;
        int gy = ty0 - 3 + r, gx = tx0 - 3 + q;
        float val = 0.f;
        if (gy >= 0 && gy < 256 && gx >= 0 && gx < 256) {
            float mm = mb[((gy >> 4) << 4) + (gx >> 4)];
            val = vc[gy * 256 + gx] * (1.f - mm);
        }
        vs[r][q] = val;
    }
    float w1[9], w2[9];
#pragma unroll
    for (int i = 0; i < 9; i++) { w1[i] = Wd1[c * 9 + i]; w2[i] = Wd2[c * 9 + i]; }
    float b1 = bd1[c], b2 = bd2[c];
    __syncthreads();

    for (int i = tid; i < 36 * 36; i += 256) {
        int r = i / 36, q = i - r * 36;
        int gy = ty0 - 2 + r, gx = tx0 - 2 + q;
        float s = 0.f;
        if (gy >= 0 && gy < 256 && gx >= 0 && gx < 256) {
            s = b1;
#pragma unroll
            for (int dy = 0; dy < 3; dy++)
#pragma unroll
                for (int dx = 0; dx < 3; dx++)
                    s = fmaf(w1[dy * 3 + dx], vs[r + dy][q + dx], s);
        }
        y1[r][q] = s;
    }
    __syncthreads();

    for (int i = tid; i < 32 * 32; i += 256) {
        int r = i >> 5, q = i & 31;
        float s = b2;
#pragma unroll
        for (int dy = 0; dy < 3; dy++)
#pragma unroll
            for (int dx = 0; dx < 3; dx++)
                s = fmaf(w2[dy * 3 + dx], y1[r + 2 * dy][q + 2 * dx], s);
        size_t idx = ((size_t)b * Cc + c) * HW + (size_t)(ty0 + r) * 256 + tx0 + q;
        fs[idx] += s;
    }
}

// =====================================================================
extern "C" void kernel_launch(void* const* d_in, const int* in_sizes, int n_in,
                              void* d_out, int out_size) {
    const float* x   = (const float*)d_in[0];
    const float* Wv  = (const float*)d_in[1];
    const float* bv  = (const float*)d_in[2];
    const float* Wt  = (const float*)d_in[3];
    const float* bt  = (const float*)d_in[4];
    const float* th  = (const float*)d_in[5];
    const float* Wq  = (const float*)d_in[6];
    const float* bq  = (const float*)d_in[7];
    const float* Wk  = (const float*)d_in[8];
    const float* bk  = (const float*)d_in[9];
    const float* Wd1 = (const float*)d_in[10];
    const float* bd1 = (const float*)d_in[11];
    const float* Wd2 = (const float*)d_in[12];
    const float* bd2 = (const float*)d_in[13];
    const float* Wo  = (const float*)d_in[14];
    const float* bo  = (const float*)d_in[15];
    float* out = (float*)d_out;

    float *pv, *pfs, *pm;
    cudaGetSymbolAddress((void**)&pv,  g_v);
    cudaGetSymbolAddress((void**)&pfs, g_fs);
    cudaGetSymbolAddress((void**)&pm,  g_mask);
    cudaFuncSetAttribute(k_gemm, cudaFuncAttributeMaxDynamicSharedMemorySize, GEMM_SMEM);
    cudaFuncSetAttribute(k_attn, cudaFuncAttributeMaxDynamicSharedMemorySize, ATTN_SMEM);

    // K1: v = Wv @ x + bv
    k_gemm<<<dim3(HW / 128, Bb), 256, GEMM_SMEM>>>(x, Wv, bv, pv);
    // K2: window stats + mask
    k_mask<<<Bb * NWIN, 256>>>(pv, Wt, bt, th, pm);
    // K3: attention (writes every pixel of fsum: f for active, 0 otherwise)
    k_attn<<<Bb * NWIN, 256, ATTN_SMEM>>>(x, Wq, bq, Wk, bk, pm, pv, pfs);
    // K4: fused double depthwise conv on v2, accumulate into fsum
    k_dw<<<dim3(64, Cc, Bb), 256>>>(pv, pm, Wd1, bd1, Wd2, bd2, pfs);
    // K5: out = Wo @ fsum + bo
    k_gemm<<<dim3(HW / 128, Bb), 256, GEMM_SMEM>>>(pfs, Wo, bo, out);
}

// round 4
// speedup vs baseline: 1.3498x; 1.3498x over previous
#include <cuda_runtime.h>
#include <math.h>

#define Bb 8
#define Cc 96
#define HW 65536
#define NWIN 256   // windows per batch (16x16)
#define SHARP 10.0f

// ---------------- scratch (device globals; no allocation) ----------------
__device__ float g_v [(size_t)Bb * Cc * HW];   // v_img
__device__ float g_fs[(size_t)Bb * Cc * HW];   // v2c then += f
__device__ float g_mask[Bb * NWIN];            // per-window mask value

// =====================================================================
// K1/K5: conv1x1 GEMM  out[b,o,p] = bias[o] + sum_c W[o,c]*in[b,c,p]
// tile: 96 c_out x 128 pixels. 256 threads, reg tile 6x8.
// K chunked (32) with double buffer: smem 68KB -> 3 blocks/SM.
// =====================================================================
#define GEMM_SMEM ((96 * 96 + 2 * 32 * 128) * 4)

__global__ void __launch_bounds__(256, 3) k_gemm(const float* __restrict__ in,
                                                 const float* __restrict__ Wm,
                                                 const float* __restrict__ bias,
                                                 float* __restrict__ out) {
    extern __shared__ float sm[];
    float* Ws = sm;              // [96][96]
    float* xs = sm + 96 * 96;    // [2][32][128]
    int b  = blockIdx.y;
    int p0 = blockIdx.x * 128;
    int tid = threadIdx.x;
    const float* inb = in + (size_t)b * Cc * HW + p0;

    for (int i = tid; i < 96 * 96; i += 256) Ws[i] = Wm[i];

    // stage chunk 0
    {
        float* dst = xs;
#pragma unroll
        for (int j = 0; j < 4; j++) {
            int idx = tid + j * 256;
            int rr = idx >> 5, qq = (idx & 31) << 2;
            *reinterpret_cast<float4*>(&dst[rr * 128 + qq]) =
                *reinterpret_cast<const float4*>(&inb[(size_t)rr * HW + qq]);
        }
    }
    __syncthreads();

    int pg = tid & 15, cg = tid >> 4;
    float acc[6][8];
#pragma unroll
    for (int i = 0; i < 6; i++)
#pragma unroll
        for (int j = 0; j < 8; j++) acc[i][j] = 0.f;

#pragma unroll 1
    for (int kc = 0; kc < 3; kc++) {
        if (kc < 2) {   // prefetch next chunk into other buffer
            float* dst = xs + ((kc + 1) & 1) * 4096;
            const float* src = inb + (size_t)(kc + 1) * 32 * HW;
#pragma unroll
            for (int j = 0; j < 4; j++) {
                int idx = tid + j * 256;
                int rr = idx >> 5, qq = (idx & 31) << 2;
                *reinterpret_cast<float4*>(&dst[rr * 128 + qq]) =
                    *reinterpret_cast<const float4*>(&src[(size_t)rr * HW + qq]);
            }
        }
        const float* xb = xs + (kc & 1) * 4096;
        const float* wb = Ws + kc * 32;
#pragma unroll 8
        for (int k = 0; k < 32; k++) {
            float a[6];
#pragma unroll
            for (int i = 0; i < 6; i++) a[i] = wb[(cg * 6 + i) * 96 + k];
            float4 x0 = *reinterpret_cast<const float4*>(&xb[k * 128 + pg * 8]);
            float4 x1 = *reinterpret_cast<const float4*>(&xb[k * 128 + pg * 8 + 4]);
            float xv[8] = {x0.x, x0.y, x0.z, x0.w, x1.x, x1.y, x1.z, x1.w};
#pragma unroll
            for (int i = 0; i < 6; i++)
#pragma unroll
                for (int j = 0; j < 8; j++) acc[i][j] = fmaf(a[i], xv[j], acc[i][j]);
        }
        __syncthreads();
    }

    float* outb = out + (size_t)b * Cc * HW + p0;
#pragma unroll
    for (int i = 0; i < 6; i++) {
        int o = cg * 6 + i;
        float bb = bias[o];
        float4 r0 = make_float4(acc[i][0] + bb, acc[i][1] + bb, acc[i][2] + bb, acc[i][3] + bb);
        float4 r1 = make_float4(acc[i][4] + bb, acc[i][5] + bb, acc[i][6] + bb, acc[i][7] + bb);
        *reinterpret_cast<float4*>(outb + (size_t)o * HW + pg * 8)     = r0;
        *reinterpret_cast<float4*>(outb + (size_t)o * HW + pg * 8 + 4) = r1;
    }
}

// =====================================================================
// K2: per-window t = mean_o leaky(Wt.v + bt); var(ddof=1); mask
// =====================================================================
__global__ void __launch_bounds__(256) k_mask(const float* __restrict__ v,
                                              const float* __restrict__ Wt,
                                              const float* __restrict__ bt,
                                              const float* __restrict__ th,
                                              float* __restrict__ mask) {
    __shared__ float Wts[24 * 96];
    __shared__ float bts[24];
    __shared__ float rs1[8], rs2[8];
    int w  = blockIdx.x;
    int b  = w >> 8, wi = w & 255;
    int wy = wi >> 4, wx = wi & 15;
    int tid = threadIdx.x;

    for (int i = tid; i < 24 * 96; i += 256) Wts[i] = Wt[i];
    if (tid < 24) bts[tid] = bt[tid];
    __syncthreads();

    int y = wy * 16 + (tid >> 4), x = wx * 16 + (tid & 15);
    const float* vp = v + (size_t)b * Cc * HW + (size_t)y * 256 + x;
    float vr[96];
#pragma unroll
    for (int c = 0; c < 96; c++) vr[c] = vp[(size_t)c * HW];

    float t = 0.f;
    for (int o = 0; o < 24; o++) {
        float s = bts[o];
        const float* wr = &Wts[o * 96];
#pragma unroll
        for (int c = 0; c < 96; c++) s = fmaf(wr[c], vr[c], s);
        t += (s >= 0.f) ? s : 0.1f * s;
    }
    t *= (1.f / 24.f);

    float s1 = t, s2 = t * t;
#pragma unroll
    for (int off = 16; off; off >>= 1) {
        s1 += __shfl_xor_sync(0xffffffffu, s1, off);
        s2 += __shfl_xor_sync(0xffffffffu, s2, off);
    }
    if ((tid & 31) == 0) { rs1[tid >> 5] = s1; rs2[tid >> 5] = s2; }
    __syncthreads();
    if (tid == 0) {
        float S1 = 0.f, S2 = 0.f;
#pragma unroll
        for (int i = 0; i < 8; i++) { S1 += rs1[i]; S2 += rs2[i]; }
        float var  = (S2 - S1 * S1 * (1.f / 256.f)) * (1.f / 255.f);
        float soft = 1.f - 1.f / (1.f + expf(-SHARP * (th[0] - var)));
        float bin  = (soft > 0.5f) ? 1.f : 0.f;
        mask[w]    = (bin - soft) + soft;   // numerically == bin (ref formula)
    }
}

// =====================================================================
// K4: fused depthwise chain: v2 = v*(1-m); y1 = dw3(v2,d1); y2 = dw3(y1,d2)
// fs = y2 (plain store). 64x32 tile, vectorized LDS128 conv, interior fast path.
// =====================================================================
__global__ void __launch_bounds__(256) k_dw(const float* __restrict__ v,
                                            const float* __restrict__ mask,
                                            const float* __restrict__ Wd1,
                                            const float* __restrict__ bd1,
                                            const float* __restrict__ Wd2,
                                            const float* __restrict__ bd2,
                                            float* __restrict__ fs) {
    __shared__ float vs[38][72];
    __shared__ float y1[36][72];
    int tx0 = blockIdx.x << 6;        // 0,64,128,192
    int ty0 = blockIdx.y << 5;        // 0..224
    int bc  = blockIdx.z;             // b*96 + c
    int c = bc % Cc, b = bc / Cc;
    int tid = threadIdx.x;
    const float* vc = v + (size_t)bc * HW;
    const float* mb = mask + b * NWIN;
    bool interior = (tx0 > 0) && (tx0 + 64 < 256) && (ty0 > 0) && (ty0 + 32 < 256);

    int lane = tid & 31, wid = tid >> 5;

    // ---- phase A: load halo tile (v * (1-mask)) ----
    if (interior) {
        for (int r = wid; r < 38; r += 8) {
            int gy = ty0 - 3 + r;
            const float* row = vc + gy * 256 + tx0 - 3;
            int mrow = (gy >> 4) << 4;
#pragma unroll
            for (int jj = 0; jj < 3; jj++) {
                int j = lane + jj * 32;
                if (j < 70) {
                    int gx = tx0 - 3 + j;
                    float mm = mb[mrow + (gx >> 4)];
                    vs[r][j] = row[j] * (1.f - mm);
                }
            }
        }
    } else {
        for (int r = wid; r < 38; r += 8) {
            int gy = ty0 - 3 + r;
#pragma unroll
            for (int jj = 0; jj < 3; jj++) {
                int j = lane + jj * 32;
                if (j < 70) {
                    int gx = tx0 - 3 + j;
                    float val = 0.f;
                    if (gy >= 0 && gy < 256 && gx >= 0 && gx < 256) {
                        float mm = mb[((gy >> 4) << 4) + (gx >> 4)];
                        val = vc[gy * 256 + gx] * (1.f - mm);
                    }
                    vs[r][j] = val;
                }
            }
        }
    }

    float w1[9], w2[9];
#pragma unroll
    for (int i = 0; i < 9; i++) { w1[i] = Wd1[c * 9 + i]; w2[i] = Wd2[c * 9 + i]; }
    float b1 = bd1[c], b2 = bd2[c];
    __syncthreads();

    // ---- phase B: conv1 (dil 1) -> y1[36][68] ----
    if (interior) {
        for (int i = tid; i < 36 * 17; i += 256) {
            int r = i / 17, q = (i - r * 17) << 2;
            float4 a0 = *reinterpret_cast<const float4*>(&vs[r][q]);
            float4 a1 = *reinterpret_cast<const float4*>(&vs[r][q + 4]);
            float4 d0 = *reinterpret_cast<const float4*>(&vs[r + 1][q]);
            float4 d1 = *reinterpret_cast<const float4*>(&vs[r + 1][q + 4]);
            float4 e0 = *reinterpret_cast<const float4*>(&vs[r + 2][q]);
            float4 e1 = *reinterpret_cast<const float4*>(&vs[r + 2][q + 4]);
            float ra[8] = {a0.x, a0.y, a0.z, a0.w, a1.x, a1.y, a1.z, a1.w};
            float rb[8] = {d0.x, d0.y, d0.z, d0.w, d1.x, d1.y, d1.z, d1.w};
            float rc[8] = {e0.x, e0.y, e0.z, e0.w, e1.x, e1.y, e1.z, e1.w};
            float o[4];
#pragma unroll
            for (int j = 0; j < 4; j++) {
                float s = b1;
                s = fmaf(w1[0], ra[j], s); s = fmaf(w1[1], ra[j + 1], s); s = fmaf(w1[2], ra[j + 2], s);
                s = fmaf(w1[3], rb[j], s); s = fmaf(w1[4], rb[j + 1], s); s = fmaf(w1[5], rb[j + 2], s);
                s = fmaf(w1[6], rc[j], s); s = fmaf(w1[7], rc[j + 1], s); s = fmaf(w1[8], rc[j + 2], s);
                o[j] = s;
            }
            *reinterpret_cast<float4*>(&y1[r][q]) = make_float4(o[0], o[1], o[2], o[3]);
        }
    } else {
        for (int i = tid; i < 36 * 68; i += 256) {
            int r = i / 68, q = i - r * 68;
            int gy = ty0 - 2 + r, gx = tx0 - 2 + q;
            float s = 0.f;
            if (gy >= 0 && gy < 256 && gx >= 0 && gx < 256) {
                s = b1;
#pragma unroll
                for (int dy = 0; dy < 3; dy++)
#pragma unroll
                    for (int dx = 0; dx < 3; dx++)
                        s = fmaf(w1[dy * 3 + dx], vs[r + dy][q + dx], s);
            }
            y1[r][q] = s;
        }
    }
    __syncthreads();

    // ---- phase C: conv2 (dil 2), plain store to fs ----
#pragma unroll
    for (int it = 0; it < 2; it++) {
        int i = tid + it * 256;
        int r = i >> 4, q = (i & 15) << 2;
        float4 p0 = *reinterpret_cast<const float4*>(&y1[r][q]);
        float4 p1 = *reinterpret_cast<const float4*>(&y1[r][q + 4]);
        float4 q0 = *reinterpret_cast<const float4*>(&y1[r + 2][q]);
        float4 q1 = *reinterpret_cast<const float4*>(&y1[r + 2][q + 4]);
        float4 s0 = *reinterpret_cast<const float4*>(&y1[r + 4][q]);
        float4 s1 = *reinterpret_cast<const float4*>(&y1[r + 4][q + 4]);
        float rp[8] = {p0.x, p0.y, p0.z, p0.w, p1.x, p1.y, p1.z, p1.w};
        float rq[8] = {q0.x, q0.y, q0.z, q0.w, q1.x, q1.y, q1.z, q1.w};
        float rs[8] = {s0.x, s0.y, s0.z, s0.w, s1.x, s1.y, s1.z, s1.w};
        float o[4];
#pragma unroll
        for (int j = 0; j < 4; j++) {
            float s = b2;
            s = fmaf(w2[0], rp[j], s); s = fmaf(w2[1], rp[j + 2], s); s = fmaf(w2[2], rp[j + 4], s);
            s = fmaf(w2[3], rq[j], s); s = fmaf(w2[4], rq[j + 2], s); s = fmaf(w2[5], rq[j + 4], s);
            s = fmaf(w2[6], rs[j], s); s = fmaf(w2[7], rs[j + 2], s); s = fmaf(w2[8], rs[j + 4], s);
            o[j] = s;
        }
        size_t idx = (size_t)bc * HW + (size_t)(ty0 + r) * 256 + tx0 + q;
        *reinterpret_cast<float4*>(&fs[idx]) = make_float4(o[0], o[1], o[2], o[3]);
    }
}

// =====================================================================
// K3: window attention, ADDITIVE into fs (runs after k_dw).
// Inactive window -> early exit (f ~ 1e-8 ~ 0).
// =====================================================================
#define ATTN_SMEM (2 * 256 * 97 * 4)

__global__ void __launch_bounds__(256) k_attn(const float* __restrict__ x,
                                              const float* __restrict__ Wq,
                                              const float* __restrict__ bq,
                                              const float* __restrict__ Wk,
                                              const float* __restrict__ bk,
                                              const float* __restrict__ mask,
                                              const float* __restrict__ v,
                                              float* __restrict__ fs) {
    extern __shared__ float sm[];
    float* xs = sm;              // [256][97], later holds q
    float* ks = sm + 256 * 97;   // [256][97]
    int w  = blockIdx.x;
    float m = mask[w];
    if (m < 0.5f) return;

    int b  = w >> 8, wi = w & 255;
    int wy = wi >> 4, wx = wi & 15;
    int y0 = wy * 16, x0 = wx * 16;
    int tid = threadIdx.x;
    size_t base = (size_t)b * Cc * HW;

    for (int i = tid; i < 96 * 256; i += 256) {
        int c = i >> 8, p = i & 255;
        xs[p * 97 + c] = x[base + (size_t)c * HW + (size_t)(y0 + (p >> 4)) * 256 + x0 + (p & 15)];
    }
    __syncthreads();

    {
        float xr[96];
#pragma unroll
        for (int c = 0; c < 96; c++) xr[c] = xs[tid * 97 + c];
#pragma unroll 1
        for (int o = 0; o < 96; o++) {
            const float* wkp = Wk + o * 96;
            const float* wqp = Wq + o * 96;
            float sk = 0.f, sq = 0.f;
#pragma unroll
            for (int c = 0; c < 96; c++) {
                sk = fmaf(wkp[c], xr[c], sk);
                sq = fmaf(wqp[c], xr[c], sq);
            }
            ks[tid * 97 + o] = bk[o] + m * sk;
            xs[tid * 97 + o] = bq[o] + m * sq;
        }
    }
    __syncthreads();

    float qr[96];
#pragma unroll
    for (int c = 0; c < 96; c++) qr[c] = xs[tid * 97 + c];
    float mx = -1e30f, li = 0.f;
#pragma unroll 1
    for (int j = 0; j < 256; j++) {
        const float* kj = &ks[j * 97];
        float s = 0.f;
#pragma unroll
        for (int c = 0; c < 96; c++) s = fmaf(qr[c], kj[c], s);
        float nm = fmaxf(mx, s);
        li = li * expf(mx - nm) + expf(s - nm);
        mx = nm;
    }
    float inv = 1.f / li;

    int yy = y0 + (tid >> 4), xxp = x0 + (tid & 15);
    size_t obase = base + (size_t)yy * 256 + xxp;
#pragma unroll 1
    for (int h = 0; h < 2; h++) {
        float fa[48];
#pragma unroll
        for (int c = 0; c < 48; c++) fa[c] = 0.f;
#pragma unroll 1
        for (int j = 0; j < 256; j++) {
            const float* kj = &ks[j * 97];
            float s = 0.f;
#pragma unroll
            for (int c = 0; c < 96; c++) s = fmaf(qr[c], kj[c], s);
            float p = expf(s - mx);
            size_t pj = (size_t)(y0 + (j >> 4)) * 256 + x0 + (j & 15);
            const float* vp = v + base + (size_t)(h * 48) * HW + pj;
#pragma unroll
            for (int c = 0; c < 48; c++) fa[c] = fmaf(p, vp[(size_t)c * HW], fa[c]);
        }
        float sc = inv * m;
#pragma unroll
        for (int c = 0; c < 48; c++)
            fs[obase + (size_t)(h * 48 + c) * HW] += fa[c] * sc;
    }
}

// =====================================================================
extern "C" void kernel_launch(void* const* d_in, const int* in_sizes, int n_in,
                              void* d_out, int out_size) {
    const float* x   = (const float*)d_in[0];
    const float* Wv  = (const float*)d_in[1];
    const float* bv  = (const float*)d_in[2];
    const float* Wt  = (const float*)d_in[3];
    const float* bt  = (const float*)d_in[4];
    const float* th  = (const float*)d_in[5];
    const float* Wq  = (const float*)d_in[6];
    const float* bq  = (const float*)d_in[7];
    const float* Wk  = (const float*)d_in[8];
    const float* bk  = (const float*)d_in[9];
    const float* Wd1 = (const float*)d_in[10];
    const float* bd1 = (const float*)d_in[11];
    const float* Wd2 = (const float*)d_in[12];
    const float* bd2 = (const float*)d_in[13];
    const float* Wo  = (const float*)d_in[14];
    const float* bo  = (const float*)d_in[15];
    float* out = (float*)d_out;

    float *pv, *pfs, *pm;
    cudaGetSymbolAddress((void**)&pv,  g_v);
    cudaGetSymbolAddress((void**)&pfs, g_fs);
    cudaGetSymbolAddress((void**)&pm,  g_mask);
    cudaFuncSetAttribute(k_gemm, cudaFuncAttributeMaxDynamicSharedMemorySize, GEMM_SMEM);
    cudaFuncSetAttribute(k_attn, cudaFuncAttributeMaxDynamicSharedMemorySize, ATTN_SMEM);

    // K1: v = Wv @ x + bv
    k_gemm<<<dim3(HW / 128, Bb), 256, GEMM_SMEM>>>(x, Wv, bv, pv);
    // K2: window stats + mask
    k_mask<<<Bb * NWIN, 256>>>(pv, Wt, bt, th, pm);
    // K4: fs = dwconv chain on v2 (plain store)
    k_dw<<<dim3(4, 8, Bb * Cc), 256>>>(pv, pm, Wd1, bd1, Wd2, bd2, pfs);
    // K3: fs += attention output (active windows only)
    k_attn<<<Bb * NWIN, 256, ATTN_SMEM>>>(x, Wq, bq, Wk, bk, pm, pv, pfs);
    // K5: out = Wo @ fs + bo
    k_gemm<<<dim3(HW / 128, Bb), 256, GEMM_SMEM>>>(pfs, Wo, bo, out);
}